// round 14
// baseline (speedup 1.0000x reference)
#include <cuda_runtime.h>

// out = cumprod_j( cos(w_j) * cos(x @ W_pre^T + b_pre) ) @ W_post^T + b_post
//
// Analytic reduction of the quantum layer:
//   z_j   = cos(q_weights_j) * cos(angle_j)
//   <Z_i> = prod_{j<=i} z_j            (CNOT chain = prefix-XOR)
//
// Block = (row pair, column half): grid=256 x 512 thr, 2 blocks/SM.
// SPLIT-K phase 1: warp w handles qubit pair {2(w&7), 2(w&7)+1} over
// K-half (w>>3). Each x half-row is read by only 8 warps -> x crossbar
// traffic halves vs full-K warps. Partial sums combined through 256 B of
// smem inside phase 2. One block barrier total.

#define NQ   16
#define DIN  1024
#define DOUT 1024
#define B    256

__global__ __launch_bounds__(512, 2)
void quantum_projector_kernel(const float* __restrict__ x,
                              const float* __restrict__ W_pre,
                              const float* __restrict__ b_pre,
                              const float* __restrict__ q_weights,
                              const float* __restrict__ W_post,
                              const float* __restrict__ b_post,
                              float* __restrict__ out)
{
    __shared__ float  s_part[2][2][NQ];  // [K-half][row][qubit] partial dots
    __shared__ float4 s_wz[16][8];       // warp-private scan slots

    const int bx   = blockIdx.x;
    const int pair = bx >> 1;            // which row pair
    const int half = bx & 1;             // which 512-column half
    const int r0   = pair * 2;
    const int r1   = r0 + 1;
    const int tid  = threadIdx.x;
    const int warp = tid >> 5;
    const int lane = tid & 31;

    // ---- Prefetch this thread's W_post column (shared by both rows) ----
    const int col = half * 512 + tid;
    const float4* __restrict__ Wp4 = reinterpret_cast<const float4*>(W_post);
    float4 wreg[4];
#pragma unroll
    for (int i = 0; i < 4; i++)
        wreg[i] = Wp4[col * 4 + i];
    const float bp = b_post[col];

    // ---- Phase 1 (split-K): warp w -> qubits {2qp, 2qp+1}, K-half kh ----
    {
        const int kh = warp >> 3;            // 0: K[0,512), 1: K[512,1024)
        const int qp = warp & 7;
        const int q0 = qp * 2, q1 = q0 + 1;
        const int kbase = kh * 128;          // float4 offset of this K-half

        const float4* __restrict__ wa4 = reinterpret_cast<const float4*>(W_pre + q0 * DIN) + kbase;
        const float4* __restrict__ wb4 = reinterpret_cast<const float4*>(W_pre + q1 * DIN) + kbase;
        const float4* __restrict__ x04 = reinterpret_cast<const float4*>(x + r0 * DIN) + kbase;
        const float4* __restrict__ x14 = reinterpret_cast<const float4*>(x + r1 * DIN) + kbase;

        float a00 = 0.f, a01 = 0.f, a10 = 0.f, a11 = 0.f;   // [row][qubit]
#pragma unroll
        for (int i = 0; i < 4; i++) {
            const int k = lane + 32 * i;     // 128 float4 per K-half, 4/lane
            const float4 wa = wa4[k];
            const float4 wb = wb4[k];
            const float4 x0 = x04[k];
            const float4 x1 = x14[k];
            a00 += x0.x * wa.x + x0.y * wa.y + x0.z * wa.z + x0.w * wa.w;
            a01 += x0.x * wb.x + x0.y * wb.y + x0.z * wb.z + x0.w * wb.w;
            a10 += x1.x * wa.x + x1.y * wa.y + x1.z * wa.z + x1.w * wa.w;
            a11 += x1.x * wb.x + x1.y * wb.y + x1.z * wb.z + x1.w * wb.w;
        }
        // 4 independent xor-reductions (pipelined shuffles)
#pragma unroll
        for (int off = 16; off >= 1; off >>= 1) {
            a00 += __shfl_xor_sync(0xffffffffu, a00, off);
            a01 += __shfl_xor_sync(0xffffffffu, a01, off);
            a10 += __shfl_xor_sync(0xffffffffu, a10, off);
            a11 += __shfl_xor_sync(0xffffffffu, a11, off);
        }
        if (lane == 0) {
            s_part[kh][0][q0] = a00;
            s_part[kh][0][q1] = a01;
            s_part[kh][1][q0] = a10;
            s_part[kh][1][q1] = a11;
        }
    }
    __syncthreads();   // the ONLY block barrier: partials ready

    // ---- Phase 2: EVERY warp combines partials + dual-row prefix scan ----
    // lanes 0..15 -> row0, lanes 16..31 -> row1 (segmented shfl_up scan),
    // broadcast within the warp via its private smem slot.
    {
        const int q   = lane & 15;
        const int seg = lane >> 4;
        const float angle = s_part[0][seg][q] + s_part[1][seg][q] + b_pre[q];
        float v = __cosf(q_weights[q]) * __cosf(angle);
#pragma unroll
        for (int off = 1; off <= 8; off <<= 1) {
            float t = __shfl_up_sync(0xffffffffu, v, off);
            if (q >= off) v *= t;   // segment boundary: q < off blocks carry-in
        }
        reinterpret_cast<float*>(s_wz[warp])[lane] = v;
        __syncwarp();
    }

    // ---- Phase 3: one column x 2 rows per thread; zq via broadcast LDS.128 ----
    float d0 = bp, d1 = bp;
#pragma unroll
    for (int i = 0; i < 4; i++) {
        const float4 za = s_wz[warp][i];       // row0 qubits 4i..4i+3
        const float4 zb = s_wz[warp][4 + i];   // row1
        const float4 w  = wreg[i];
        d0 += za.x * w.x + za.y * w.y + za.z * w.z + za.w * w.w;
        d1 += zb.x * w.x + zb.y * w.y + zb.z * w.z + zb.w * w.w;
    }

    out[r0 * DOUT + col] = d0;
    out[r1 * DOUT + col] = d1;
}

extern "C" void kernel_launch(void* const* d_in, const int* in_sizes, int n_in,
                              void* d_out, int out_size)
{
    const float* x         = (const float*)d_in[0];   // [256, 1024]
    const float* W_pre     = (const float*)d_in[1];   // [16, 1024]
    const float* b_pre     = (const float*)d_in[2];   // [16]
    const float* q_weights = (const float*)d_in[3];   // [16]
    const float* W_post    = (const float*)d_in[4];   // [1024, 16]
    const float* b_post    = (const float*)d_in[5];   // [1024]
    float* out             = (float*)d_out;           // [256, 1024]

    quantum_projector_kernel<<<B, 512>>>(x, W_pre, b_pre, q_weights,
                                         W_post, b_post, out);
}

// round 15
// speedup vs baseline: 1.0294x; 1.0294x over previous
#include <cuda_runtime.h>

// out = cumprod_j( cos(w_j) * cos(x @ W_pre^T + b_pre) ) @ W_post^T + b_post
//
// Analytic reduction of the quantum layer:
//   z_j   = cos(q_weights_j) * cos(angle_j)
//   <Z_i> = prod_{j<=i} z_j            (CNOT chain = prefix-XOR)
//
// Block = (row pair, column half): grid=256 x 512 thr, 2 blocks/SM.
// SPLIT-K-4 phase 1: warp w handles qubit group 4*(w&3)..+3 over K-quarter
// (w>>2). Each x quarter-row read by only 4 warps; per-lane LDG count 12.
// Partials combined through 512 B smem inside phase 2. One block barrier.

#define NQ   16
#define DIN  1024
#define DOUT 1024
#define B    256

__global__ __launch_bounds__(512, 2)
void quantum_projector_kernel(const float* __restrict__ x,
                              const float* __restrict__ W_pre,
                              const float* __restrict__ b_pre,
                              const float* __restrict__ q_weights,
                              const float* __restrict__ W_post,
                              const float* __restrict__ b_post,
                              float* __restrict__ out)
{
    __shared__ float  s_part[4][2][NQ];  // [K-quarter][row][qubit] partial dots
    __shared__ float4 s_wz[16][8];       // warp-private scan slots

    const int bx   = blockIdx.x;
    const int pair = bx >> 1;            // which row pair
    const int half = bx & 1;             // which 512-column half
    const int r0   = pair * 2;
    const int r1   = r0 + 1;
    const int tid  = threadIdx.x;
    const int warp = tid >> 5;
    const int lane = tid & 31;

    // ---- Prefetch this thread's W_post column (shared by both rows) ----
    const int col = half * 512 + tid;
    const float4* __restrict__ Wp4 = reinterpret_cast<const float4*>(W_post);
    float4 wreg[4];
#pragma unroll
    for (int i = 0; i < 4; i++)
        wreg[i] = Wp4[col * 4 + i];
    const float bp = b_post[col];

    // ---- Phase 1 (split-K-4): warp w -> qubits 4qg..4qg+3, K-quarter kq ----
    {
        const int kq = warp >> 2;            // K-quarter 0..3
        const int qg = warp & 3;             // qubit group 0..3
        const int qb = qg * 4;               // first qubit of the group
        const int kbase = kq * 64;           // float4 offset (256 floats/quarter)

        const float4* __restrict__ x04 = reinterpret_cast<const float4*>(x + r0 * DIN) + kbase;
        const float4* __restrict__ x14 = reinterpret_cast<const float4*>(x + r1 * DIN) + kbase;
        const float4* __restrict__ wq0 = reinterpret_cast<const float4*>(W_pre + (qb + 0) * DIN) + kbase;
        const float4* __restrict__ wq1 = reinterpret_cast<const float4*>(W_pre + (qb + 1) * DIN) + kbase;
        const float4* __restrict__ wq2 = reinterpret_cast<const float4*>(W_pre + (qb + 2) * DIN) + kbase;
        const float4* __restrict__ wq3 = reinterpret_cast<const float4*>(W_pre + (qb + 3) * DIN) + kbase;

        float a0[4] = {0.f, 0.f, 0.f, 0.f};  // row0, qubits qb..qb+3
        float a1[4] = {0.f, 0.f, 0.f, 0.f};  // row1
#pragma unroll
        for (int i = 0; i < 2; i++) {
            const int k = lane + 32 * i;     // 64 float4 per quarter, 2/lane
            const float4 x0 = x04[k];
            const float4 x1 = x14[k];
            const float4 w0 = wq0[k];
            const float4 w1 = wq1[k];
            const float4 w2 = wq2[k];
            const float4 w3 = wq3[k];
            a0[0] += x0.x * w0.x + x0.y * w0.y + x0.z * w0.z + x0.w * w0.w;
            a0[1] += x0.x * w1.x + x0.y * w1.y + x0.z * w1.z + x0.w * w1.w;
            a0[2] += x0.x * w2.x + x0.y * w2.y + x0.z * w2.z + x0.w * w2.w;
            a0[3] += x0.x * w3.x + x0.y * w3.y + x0.z * w3.z + x0.w * w3.w;
            a1[0] += x1.x * w0.x + x1.y * w0.y + x1.z * w0.z + x1.w * w0.w;
            a1[1] += x1.x * w1.x + x1.y * w1.y + x1.z * w1.z + x1.w * w1.w;
            a1[2] += x1.x * w2.x + x1.y * w2.y + x1.z * w2.z + x1.w * w2.w;
            a1[3] += x1.x * w3.x + x1.y * w3.y + x1.z * w3.z + x1.w * w3.w;
        }

        // Dual-row fold per qubit: lanes<16 carry row0, lanes>=16 carry row1.
        float v[4];
#pragma unroll
        for (int j = 0; j < 4; j++) {
            a0[j] += __shfl_xor_sync(0xffffffffu, a0[j], 16);
            a1[j] += __shfl_xor_sync(0xffffffffu, a1[j], 16);
            v[j] = (lane < 16) ? a0[j] : a1[j];
        }
#pragma unroll
        for (int off = 8; off >= 1; off >>= 1) {
#pragma unroll
            for (int j = 0; j < 4; j++)
                v[j] += __shfl_xor_sync(0xffffffffu, v[j], off);
        }
        if (lane == 0) {
#pragma unroll
            for (int j = 0; j < 4; j++) s_part[kq][0][qb + j] = v[j];
        }
        if (lane == 16) {
#pragma unroll
            for (int j = 0; j < 4; j++) s_part[kq][1][qb + j] = v[j];
        }
    }
    __syncthreads();   // the ONLY block barrier: partials ready

    // ---- Phase 2: EVERY warp combines partials + dual-row prefix scan ----
    // lanes 0..15 -> row0, lanes 16..31 -> row1 (segmented shfl_up scan),
    // broadcast within the warp via its private smem slot.
    {
        const int q   = lane & 15;
        const int seg = lane >> 4;
        const float angle = s_part[0][seg][q] + s_part[1][seg][q]
                          + s_part[2][seg][q] + s_part[3][seg][q] + b_pre[q];
        float v = __cosf(q_weights[q]) * __cosf(angle);
#pragma unroll
        for (int off = 1; off <= 8; off <<= 1) {
            float t = __shfl_up_sync(0xffffffffu, v, off);
            if (q >= off) v *= t;   // segment boundary: q < off blocks carry-in
        }
        reinterpret_cast<float*>(s_wz[warp])[lane] = v;
        __syncwarp();
    }

    // ---- Phase 3: one column x 2 rows per thread; zq via broadcast LDS.128 ----
    float d0 = bp, d1 = bp;
#pragma unroll
    for (int i = 0; i < 4; i++) {
        const float4 za = s_wz[warp][i];       // row0 qubits 4i..4i+3
        const float4 zb = s_wz[warp][4 + i];   // row1
        const float4 w  = wreg[i];
        d0 += za.x * w.x + za.y * w.y + za.z * w.z + za.w * w.w;
        d1 += zb.x * w.x + zb.y * w.y + zb.z * w.z + zb.w * w.w;
    }

    out[r0 * DOUT + col] = d0;
    out[r1 * DOUT + col] = d1;
}

extern "C" void kernel_launch(void* const* d_in, const int* in_sizes, int n_in,
                              void* d_out, int out_size)
{
    const float* x         = (const float*)d_in[0];   // [256, 1024]
    const float* W_pre     = (const float*)d_in[1];   // [16, 1024]
    const float* b_pre     = (const float*)d_in[2];   // [16]
    const float* q_weights = (const float*)d_in[3];   // [16]
    const float* W_post    = (const float*)d_in[4];   // [1024, 16]
    const float* b_post    = (const float*)d_in[5];   // [1024]
    float* out             = (float*)d_out;           // [256, 1024]

    quantum_projector_kernel<<<B, 512>>>(x, W_pre, b_pre, q_weights,
                                         W_post, b_post, out);
}